// round 5
// baseline (speedup 1.0000x reference)
#include <cuda_runtime.h>
#include <cstdint>

#define EN 2048
#define IN_ 256
#define TN 256
#define BN 32
#define EWORDS 64   // uint32 words of packed exc spikes
#define IWORDS 8    // uint32 words of packed inh spikes
#define NT 512      // threads per CTA (4 exc neurons each, stride 512)

// persistent scratch (no allocation allowed)
__device__ __align__(16) uint32_t g_wrec_t[EWORDS * EN]; // transposed packed w_rec
__device__ float g_rowsum[EN];    // popcount of w_rec row j (exact integer as float)
__device__ float g_cs_wie[EN];    // sum_i w_ie[i][e] (ascending i)
__device__ float g_cs_wei[IN_];   // sum_e w_ei[e][i] (ascending e)
__device__ __align__(16) uint32_t g_outbits[(size_t)TN * BN * EWORDS]; // 2MB packed spikes

// ---------------- prep kernels (deterministic, rerun every launch) ----------------
__global__ void prep_pack(const float* __restrict__ wrec) {
    int idx = blockIdx.x * blockDim.x + threadIdx.x;  // 0 .. EN*EWORDS-1
    int j = idx >> 6, w = idx & 63;
    // w_rec entries are exactly 0.0f or 1.0f -> nonzero iff bit pattern nonzero
    const uint4* p = reinterpret_cast<const uint4*>(wrec + (size_t)j * EN + (size_t)w * 32);
    uint32_t m = 0;
#pragma unroll
    for (int k = 0; k < 8; k++) {
        uint4 f = p[k];
        m |= (f.x ? 1u : 0u) << (k * 4 + 0);
        m |= (f.y ? 1u : 0u) << (k * 4 + 1);
        m |= (f.z ? 1u : 0u) << (k * 4 + 2);
        m |= (f.w ? 1u : 0u) << (k * 4 + 3);
    }
    g_wrec_t[w * EN + j] = m;
}

__global__ void prep_sums(const float* __restrict__ wie, const float* __restrict__ wei) {
    int t = blockIdx.x * blockDim.x + threadIdx.x;  // 2048 threads
    if (t < EN) {
        int c = 0;
#pragma unroll 8
        for (int w = 0; w < EWORDS; w++) c += __popc(g_wrec_t[w * EN + t]);
        g_rowsum[t] = (float)c;
        float s = 0.f;
#pragma unroll 4
        for (int i = 0; i < IN_; i++) s = __fadd_rn(s, wie[(size_t)i * EN + t]);
        g_cs_wie[t] = s;
    }
    if (t < IN_) {
        float s = 0.f;
#pragma unroll 4
        for (int e = 0; e < EN; e++) s = __fadd_rn(s, wei[(size_t)e * IN_ + t]);
        g_cs_wei[t] = s;
    }
}

// ---------------- main simulator: one CTA per batch, one barrier per step ----------------
__global__ __launch_bounds__(NT, 1)
void sim_kernel(const float* __restrict__ x,
                const float* __restrict__ wei,
                const float* __restrict__ wie)
{
    __shared__ uint32_t s_ez[2][EWORDS];
    __shared__ uint32_t s_iz[2][IWORDS];
    __shared__ __align__(16) unsigned char s_fb[2][16];  // per-warp all/any flag bytes

    const int tid  = threadIdx.x;
    const int b    = blockIdx.x;
    const int warp = tid >> 5, lane = tid & 31;

    // register-resident state
    float v[4]  = {0.f, 0.f, 0.f, 0.f};
    float cu[4] = {0.f, 0.f, 0.f, 0.f};
    float iv = 0.f, ii = 0.f;                 // inh neuron tid (tid < 256)

    // loop-invariant constants
    float rs[4], cw[4];
#pragma unroll
    for (int j = 0; j < 4; j++) {
        rs[j] = g_rowsum[tid + NT * j];
        cw[j] = g_cs_wie[tid + NT * j];
    }
    const float cwei = (tid < IN_) ? g_cs_wei[tid] : 0.f;

    if (tid < EWORDS) { s_ez[0][tid] = 0u; s_ez[1][tid] = 0u; }
    if (tid < IWORDS) { s_iz[0][tid] = 0u; s_iz[1][tid] = 0u; }
    __syncthreads();

    // depth-2 x pipeline: xc = x[t], xn = x[t+1]
    float xc[4], xn[4];
#pragma unroll
    for (int j = 0; j < 4; j++) {
        xc[j] = x[(size_t)b * EN + tid + NT * j];
        xn[j] = x[((size_t)1 * BN + b) * EN + tid + NT * j];
    }

    int pe_all = 0, pe_any = 0, pi_all = 0, pi_any = 0;

    for (int t = 0; t < TN; t++) {
        const int wp = t & 1, rp = wp ^ 1;

        // ---- [a] cross terms from previous step's spikes ----
        float rec[4], inh[4];
        if (pe_all) {
#pragma unroll
            for (int j = 0; j < 4; j++) rec[j] = rs[j];
        } else if (!pe_any) {
#pragma unroll
            for (int j = 0; j < 4; j++) rec[j] = 0.f;
        } else {
            int c[4] = {0, 0, 0, 0};
#pragma unroll 4
            for (int w = 0; w < EWORDS; w++) {
                uint32_t ez = s_ez[rp][w];
#pragma unroll
                for (int j = 0; j < 4; j++)
                    c[j] += __popc(ez & g_wrec_t[w * EN + tid + NT * j]);
            }
#pragma unroll
            for (int j = 0; j < 4; j++) rec[j] = (float)c[j];
        }

        if (pi_all) {
#pragma unroll
            for (int j = 0; j < 4; j++) inh[j] = cw[j];
        } else if (!pi_any) {
#pragma unroll
            for (int j = 0; j < 4; j++) inh[j] = 0.f;
        } else {
            // sparse bit-scan, ascending i: exact JAX order (zero terms skipped exactly)
#pragma unroll
            for (int j = 0; j < 4; j++) inh[j] = 0.f;
            for (int w = 0; w < IWORDS; w++) {
                uint32_t m = s_iz[rp][w];
                while (m) {
                    int cbit = __ffs(m) - 1; m &= m - 1;
                    const float* wr = wie + (size_t)(w * 32 + cbit) * EN + tid;
                    inh[0] = __fadd_rn(inh[0], wr[0]);
                    inh[1] = __fadd_rn(inh[1], wr[NT]);
                    inh[2] = __fadd_rn(inh[2], wr[2 * NT]);
                    inh[3] = __fadd_rn(inh[3], wr[3 * NT]);
                }
            }
        }

        // ---- [b] excitatory update (JAX-exact rounding order) ----
        int z[4];
#pragma unroll
        for (int j = 0; j < 4; j++) {
            float id = __fadd_rn(cu[j], __fmul_rn(-0.2f, cu[j]));
            float vd = __fadd_rn(v[j], __fmul_rn(0.1f, __fadd_rn(__fsub_rn(0.f, v[j]), cu[j])));
            z[j] = __fsub_rn(vd, 1.0f) > 0.f;
            v[j] = z[j] ? 0.f : vd;
            cu[j] = __fadd_rn(__fadd_rn(id, __fsub_rn(xc[j], inh[j])), rec[j]);
        }

        // inhibitory decay + spike from OLD inh state (no dep on new ez)
        float ii_dec = __fadd_rn(ii, __fmul_rn(-0.2f, ii));
        float vi_dec = __fadd_rn(iv, __fmul_rn(0.1f, __fadd_rn(__fsub_rn(0.f, iv), ii)));
        int zi = __fsub_rn(vi_dec, 1.0f) > 0.f;   // tid>=256: state stays 0 -> zi=0
        iv = zi ? 0.f : vi_dec;

        // ---- [c] publish spikes + per-warp flag byte, output bits to global ----
        uint32_t eb0 = __ballot_sync(0xffffffffu, z[0]);
        uint32_t eb1 = __ballot_sync(0xffffffffu, z[1]);
        uint32_t eb2 = __ballot_sync(0xffffffffu, z[2]);
        uint32_t eb3 = __ballot_sync(0xffffffffu, z[3]);
        uint32_t ibal = __ballot_sync(0xffffffffu, zi);
        if (lane == 0) {
            s_ez[wp][warp]      = eb0;
            s_ez[wp][16 + warp] = eb1;
            s_ez[wp][32 + warp] = eb2;
            s_ez[wp][48 + warp] = eb3;
            uint32_t* ob = g_outbits + ((size_t)t * BN + b) * EWORDS;
            ob[warp]      = eb0;
            ob[16 + warp] = eb1;
            ob[32 + warp] = eb2;
            ob[48 + warp] = eb3;
            uint32_t ea = ((eb0 & eb1 & eb2 & eb3) == 0xffffffffu) ? 1u : 0u;
            uint32_t ey = ((eb0 | eb1 | eb2 | eb3) != 0u) ? 1u : 0u;
            uint32_t ia, iy;
            if (warp < IWORDS) {
                s_iz[wp][warp] = ibal;
                ia = (ibal == 0xffffffffu) ? 1u : 0u;
                iy = (ibal != 0u) ? 1u : 0u;
            } else { ia = 1u; iy = 0u; }   // neutral elements
            s_fb[wp][warp] = (unsigned char)(ea | (ey << 1) | (ia << 2) | (iy << 3));
        }

        // shift x pipeline and prefetch t+2 (2 steps of slack >= DRAM latency)
#pragma unroll
        for (int j = 0; j < 4; j++) xc[j] = xn[j];
        if (t + 2 < TN) {
            const float* xb2 = x + ((size_t)(t + 2) * BN + b) * EN;
#pragma unroll
            for (int j = 0; j < 4; j++) xn[j] = xb2[tid + NT * j];
        }

        __syncthreads();  // the ONLY barrier per step

        // fold 16 flag bytes with one LDS.128 + 4 ALU ops
        uint4 f = *reinterpret_cast<const uint4*>(&s_fb[wp][0]);
        uint32_t fand = f.x & f.y & f.z & f.w;
        uint32_t forr = f.x | f.y | f.z | f.w;
        fand &= fand >> 16; fand &= fand >> 8;
        forr |= forr >> 16; forr |= forr >> 8;
        int ne_all = fand & 1, ne_any = (forr >> 1) & 1;
        int ni_all = (fand >> 2) & 1, ni_any = (forr >> 3) & 1;

        // ---- [d] inhibitory current update with NEW exc spikes ----
        if (tid < IN_) {
            float xi;
            if (ne_all)       xi = cwei;
            else if (!ne_any) xi = 0.f;
            else {
                xi = 0.f;
                for (int w = 0; w < EWORDS; w++) {
                    uint32_t m = s_ez[wp][w];
                    while (m) {
                        int cbit = __ffs(m) - 1; m &= m - 1;
                        xi = __fadd_rn(xi, wei[(size_t)(w * 32 + cbit) * IN_ + tid]);
                    }
                }
            }
            ii = __fadd_rn(ii_dec, xi);
        }
        pe_all = ne_all; pe_any = ne_any; pi_all = ni_all; pi_any = ni_any;
        // buffer reuse safety: buffer wp's readers ([d] here, [a] next step) all
        // complete before sync_{t+1}; next writer of wp is step t+2, after sync_{t+1}.
    }
}

// ---------------- expand packed bits -> float32 output (fully parallel) ----------------
__global__ void expand_kernel(float* __restrict__ out) {
    int w = blockIdx.x * blockDim.x + threadIdx.x;   // word index, one per 32 output floats
    uint32_t bits = g_outbits[w];
    float4* o = reinterpret_cast<float4*>(out + (size_t)w * 32);
#pragma unroll
    for (int q = 0; q < 8; q++) {
        float4 f;
        f.x = (bits >> (q * 4 + 0)) & 1u ? 1.f : 0.f;
        f.y = (bits >> (q * 4 + 1)) & 1u ? 1.f : 0.f;
        f.z = (bits >> (q * 4 + 2)) & 1u ? 1.f : 0.f;
        f.w = (bits >> (q * 4 + 3)) & 1u ? 1.f : 0.f;
        __stcs(&o[q], f);   // streaming store: don't evict x from L2
    }
}

extern "C" void kernel_launch(void* const* d_in, const int* in_sizes, int n_in,
                              void* d_out, int out_size)
{
    const float* x     = (const float*)d_in[0];  // [T,B,E]
    // d_in[1] = w_in (identity) -- exact pass-through, unused
    const float* w_rec = (const float*)d_in[2];  // [E,E]
    const float* w_ei  = (const float*)d_in[3];  // [E,I]
    const float* w_ie  = (const float*)d_in[4];  // [I,E]
    float* out = (float*)d_out;

    prep_pack<<<(EN * EWORDS) / 256, 256>>>(w_rec);
    prep_sums<<<8, 256>>>(w_ie, w_ei);
    sim_kernel<<<BN, NT>>>(x, w_ei, w_ie);
    expand_kernel<<<(TN * BN * EWORDS) / 256, 256>>>(out);
}

// round 6
// speedup vs baseline: 1.2040x; 1.2040x over previous
#include <cuda_runtime.h>
#include <cstdint>

#define EN 2048
#define IN_ 256
#define TN 256
#define BN 32
#define EWORDS 64
#define IWORDS 8
#define NT 512      // threads per CTA (4 exc neurons each, stride 512)

// persistent scratch (no allocation allowed)
__device__ __align__(16) uint32_t g_wrec_t[EWORDS * EN]; // transposed packed w_rec
__device__ float g_rowsum[EN];    // popcount of w_rec row j (exact integer as float)
__device__ float g_cs_wie[EN];    // sum_i w_ie[i][e] (ascending i)
__device__ float g_cs_wei[IN_];   // sum_e w_ei[e][i] (ascending e)
// saturation-invariant bounds (reset in prep_pack, filled in prep_rest)
__device__ int      g_rsmin;      // min_j rowsum[j]
__device__ uint32_t g_cwie_max_u; // max_e cs_wie[e]   (float bits, values >= 0)
__device__ uint32_t g_cwei_min_u; // min_i cs_wei[i]   (float bits, values >= 0)
__device__ uint32_t g_xmax_u;     // max |x|           (float bits)

// ---------------- prep 1: pack w_rec bits (+ reset reduction targets) ----------------
__global__ void prep_pack(const float* __restrict__ wrec) {
    if (blockIdx.x == 0 && threadIdx.x == 0) {
        g_rsmin = 0x7fffffff;
        g_cwie_max_u = 0u;
        g_cwei_min_u = 0x7f7fffffu;  // FLT_MAX bits
        g_xmax_u = 0u;
    }
    int idx = blockIdx.x * blockDim.x + threadIdx.x;  // 0 .. EN*EWORDS-1
    int j = idx >> 6, w = idx & 63;
    // w_rec entries are exactly 0.0f or 1.0f -> nonzero iff bit pattern nonzero
    const uint4* p = reinterpret_cast<const uint4*>(wrec + (size_t)j * EN + (size_t)w * 32);
    uint32_t m = 0;
#pragma unroll
    for (int k = 0; k < 8; k++) {
        uint4 f = p[k];
        m |= (f.x ? 1u : 0u) << (k * 4 + 0);
        m |= (f.y ? 1u : 0u) << (k * 4 + 1);
        m |= (f.z ? 1u : 0u) << (k * 4 + 2);
        m |= (f.w ? 1u : 0u) << (k * 4 + 3);
    }
    g_wrec_t[w * EN + j] = m;
}

// ---------------- prep 2: sums + invariant bounds + max|x| scan ----------------
__global__ void prep_rest(const float* __restrict__ wie, const float* __restrict__ wei,
                          const float* __restrict__ x) {
    const int tid = threadIdx.x, lane = tid & 31;
    if (blockIdx.x < 8) {
        int t = blockIdx.x * 256 + tid;  // 0..2047
        int c = 0;
#pragma unroll 8
        for (int w = 0; w < EWORDS; w++) c += __popc(g_wrec_t[w * EN + t]);
        g_rowsum[t] = (float)c;
        atomicMin(&g_rsmin, c);
        float s = 0.f;
#pragma unroll 4
        for (int i = 0; i < IN_; i++) s = __fadd_rn(s, wie[(size_t)i * EN + t]);
        g_cs_wie[t] = s;
        atomicMax(&g_cwie_max_u, __float_as_uint(s));  // s >= 0: bits monotone
        if (t < IN_) {
            float q = 0.f;
#pragma unroll 4
            for (int e = 0; e < EN; e++) q = __fadd_rn(q, wei[(size_t)e * IN_ + t]);
            g_cs_wei[t] = q;
            atomicMin(&g_cwei_min_u, __float_as_uint(q));
        }
    } else {
        // blocks 8..263: max |x| over all T*B*E floats (as float4)
        const float4* x4 = reinterpret_cast<const float4*>(x);
        const int n4 = (TN * BN * EN) / 4;
        int i = (blockIdx.x - 8) * 256 + tid;
        const int stride = 256 * 256;
        float m = 0.f;
        for (; i < n4; i += stride) {
            float4 f = x4[i];
            m = fmaxf(m, fmaxf(fmaxf(fabsf(f.x), fabsf(f.y)), fmaxf(fabsf(f.z), fabsf(f.w))));
        }
#pragma unroll
        for (int off = 16; off > 0; off >>= 1)
            m = fmaxf(m, __shfl_xor_sync(0xffffffffu, m, off));
        if (lane == 0) atomicMax(&g_xmax_u, __float_as_uint(m));
    }
}

// ---------------- main simulator: one CTA per batch, early exit on saturation ----------------
__global__ __launch_bounds__(NT, 1)
void sim_kernel(const float* __restrict__ x,
                const float* __restrict__ wei,
                const float* __restrict__ wie,
                float* __restrict__ out)
{
    __shared__ uint32_t s_ez[2][EWORDS];
    __shared__ uint32_t s_iz[2][IWORDS];
    __shared__ __align__(16) unsigned char s_fb[2][16];  // per-warp flag bytes

    const int tid  = threadIdx.x;
    const int b    = blockIdx.x;
    const int warp = tid >> 5, lane = tid & 31;

    float v[4]  = {0.f, 0.f, 0.f, 0.f};
    float cu[4] = {0.f, 0.f, 0.f, 0.f};
    float iv = 0.f, ii = 0.f;                 // inh neuron tid (tid < 256)

    float rs[4], cw[4];
#pragma unroll
    for (int j = 0; j < 4; j++) {
        rs[j] = g_rowsum[tid + NT * j];
        cw[j] = g_cs_wie[tid + NT * j];
    }
    const float cwei = (tid < IN_) ? g_cs_wei[tid] : 0.f;

    // saturation-invariant enabling condition (data-dependent, proven sufficient):
    //   margin = rowsum_min - max(cs_wie) - max|x| >= 13  and  min(cs_wei) >= 13
    const int g_ok =
        (__fadd_rn((float)g_rsmin,
                   -__fadd_rn(__uint_as_float(g_cwie_max_u), __uint_as_float(g_xmax_u))) >= 13.0f)
        && (__uint_as_float(g_cwei_min_u) >= 13.0f);

    if (tid < EWORDS) { s_ez[0][tid] = 0u; s_ez[1][tid] = 0u; }
    if (tid < IWORDS) { s_iz[0][tid] = 0u; s_iz[1][tid] = 0u; }
    __syncthreads();

    float xc[4], xn[4];
#pragma unroll
    for (int j = 0; j < 4; j++) {
        xc[j] = x[(size_t)b * EN + tid + NT * j];
        xn[j] = x[((size_t)1 * BN + b) * EN + tid + NT * j];
    }

    int pe_all = 0, pe_any = 0, pi_all = 0, pi_any = 0;
    int ts = TN - 1;   // last simulated step

    for (int t = 0; t < TN; t++) {
        const int wp = t & 1, rp = wp ^ 1;

        // ---- [a] cross terms from previous step's spikes ----
        float rec[4], inh[4];
        if (pe_all) {
#pragma unroll
            for (int j = 0; j < 4; j++) rec[j] = rs[j];
        } else if (!pe_any) {
#pragma unroll
            for (int j = 0; j < 4; j++) rec[j] = 0.f;
        } else {
            int c[4] = {0, 0, 0, 0};
#pragma unroll 4
            for (int w = 0; w < EWORDS; w++) {
                uint32_t ez = s_ez[rp][w];
#pragma unroll
                for (int j = 0; j < 4; j++)
                    c[j] += __popc(ez & g_wrec_t[w * EN + tid + NT * j]);
            }
#pragma unroll
            for (int j = 0; j < 4; j++) rec[j] = (float)c[j];
        }

        if (pi_all) {
#pragma unroll
            for (int j = 0; j < 4; j++) inh[j] = cw[j];
        } else if (!pi_any) {
#pragma unroll
            for (int j = 0; j < 4; j++) inh[j] = 0.f;
        } else {
            // sparse bit-scan, ascending i: exact JAX summation order
#pragma unroll
            for (int j = 0; j < 4; j++) inh[j] = 0.f;
            for (int w = 0; w < IWORDS; w++) {
                uint32_t m = s_iz[rp][w];
                while (m) {
                    int cbit = __ffs(m) - 1; m &= m - 1;
                    const float* wr = wie + (size_t)(w * 32 + cbit) * EN + tid;
                    inh[0] = __fadd_rn(inh[0], wr[0]);
                    inh[1] = __fadd_rn(inh[1], wr[NT]);
                    inh[2] = __fadd_rn(inh[2], wr[2 * NT]);
                    inh[3] = __fadd_rn(inh[3], wr[3 * NT]);
                }
            }
        }

        // ---- [b] excitatory update (JAX-exact rounding order) + direct output ----
        int z[4];
        float* orow = out + ((size_t)t * BN + b) * EN;
#pragma unroll
        for (int j = 0; j < 4; j++) {
            float id = __fadd_rn(cu[j], __fmul_rn(-0.2f, cu[j]));
            float vd = __fadd_rn(v[j], __fmul_rn(0.1f, __fadd_rn(__fsub_rn(0.f, v[j]), cu[j])));
            z[j] = __fsub_rn(vd, 1.0f) > 0.f;
            v[j] = z[j] ? 0.f : vd;
            cu[j] = __fadd_rn(__fadd_rn(id, __fsub_rn(xc[j], inh[j])), rec[j]);
            __stcs(&orow[tid + NT * j], z[j] ? 1.f : 0.f);
        }

        // inhibitory decay + spike from OLD inh state
        float ii_dec = __fadd_rn(ii, __fmul_rn(-0.2f, ii));
        float vi_dec = __fadd_rn(iv, __fmul_rn(0.1f, __fadd_rn(__fsub_rn(0.f, iv), ii)));
        int zi = __fsub_rn(vi_dec, 1.0f) > 0.f;   // tid>=256: stays 0
        iv = zi ? 0.f : vi_dec;

        // per-thread saturation-stability predicate (uses i_t just computed and ii_{t-1})
        int stable = g_ok && z[0] && z[1] && z[2] && z[3]
                   && (cu[0] >= 64.f) && (cu[1] >= 64.f) && (cu[2] >= 64.f) && (cu[3] >= 64.f)
                   && (tid >= IN_ || (zi && ii >= 64.f));

        // ---- [c] publish spikes + per-warp flag byte ----
        uint32_t eb0 = __ballot_sync(0xffffffffu, z[0]);
        uint32_t eb1 = __ballot_sync(0xffffffffu, z[1]);
        uint32_t eb2 = __ballot_sync(0xffffffffu, z[2]);
        uint32_t eb3 = __ballot_sync(0xffffffffu, z[3]);
        uint32_t ibal = __ballot_sync(0xffffffffu, zi);
        uint32_t sbal = __ballot_sync(0xffffffffu, stable);
        if (lane == 0) {
            s_ez[wp][warp]      = eb0;
            s_ez[wp][16 + warp] = eb1;
            s_ez[wp][32 + warp] = eb2;
            s_ez[wp][48 + warp] = eb3;
            uint32_t ea = ((eb0 & eb1 & eb2 & eb3) == 0xffffffffu) ? 1u : 0u;
            uint32_t ey = ((eb0 | eb1 | eb2 | eb3) != 0u) ? 1u : 0u;
            uint32_t sa = (sbal == 0xffffffffu) ? 1u : 0u;
            uint32_t ia, iy;
            if (warp < IWORDS) {
                s_iz[wp][warp] = ibal;
                ia = (ibal == 0xffffffffu) ? 1u : 0u;
                iy = (ibal != 0u) ? 1u : 0u;
            } else { ia = 1u; iy = 0u; }   // neutral elements
            s_fb[wp][warp] = (unsigned char)(ea | (ey << 1) | (ia << 2) | (iy << 3) | (sa << 4));
        }

        // shift x pipeline and prefetch t+2
#pragma unroll
        for (int j = 0; j < 4; j++) xc[j] = xn[j];
        if (t + 2 < TN) {
            const float* xb2 = x + ((size_t)(t + 2) * BN + b) * EN;
#pragma unroll
            for (int j = 0; j < 4; j++) xn[j] = xb2[tid + NT * j];
        }

        __syncthreads();  // the ONLY barrier per step

        uint4 f = *reinterpret_cast<const uint4*>(&s_fb[wp][0]);
        uint32_t fand = f.x & f.y & f.z & f.w;
        uint32_t forr = f.x | f.y | f.z | f.w;
        fand &= fand >> 16; fand &= fand >> 8;
        forr |= forr >> 16; forr |= forr >> 8;
        int ne_all = fand & 1, ne_any = (forr >> 1) & 1;
        int ni_all = (fand >> 2) & 1, ni_any = (forr >> 3) & 1;

        if ((fand >> 4) & 1) { ts = t; break; }  // absorbing saturation: uniform exit

        // ---- [d] inhibitory current update with NEW exc spikes ----
        if (tid < IN_) {
            float xi;
            if (ne_all)       xi = cwei;
            else if (!ne_any) xi = 0.f;
            else {
                xi = 0.f;
                for (int w = 0; w < EWORDS; w++) {
                    uint32_t m = s_ez[wp][w];
                    while (m) {
                        int cbit = __ffs(m) - 1; m &= m - 1;
                        xi = __fadd_rn(xi, wei[(size_t)(w * 32 + cbit) * IN_ + tid]);
                    }
                }
            }
            ii = __fadd_rn(ii_dec, xi);
        }
        pe_all = ne_all; pe_any = ne_any; pi_all = ni_all; pi_any = ni_any;
    }

    // ---- bulk fill: all remaining rows of this batch are all-ones ----
    const float4 ones = make_float4(1.f, 1.f, 1.f, 1.f);
    for (int t = ts + 1; t < TN; t++) {
        float4* orow = reinterpret_cast<float4*>(out + ((size_t)t * BN + b) * EN);
        __stcs(&orow[tid], ones);   // 512 threads x 16B = full 2048-float row
    }
}

extern "C" void kernel_launch(void* const* d_in, const int* in_sizes, int n_in,
                              void* d_out, int out_size)
{
    const float* x     = (const float*)d_in[0];  // [T,B,E]
    // d_in[1] = w_in (identity) -- exact pass-through, unused
    const float* w_rec = (const float*)d_in[2];  // [E,E]
    const float* w_ei  = (const float*)d_in[3];  // [E,I]
    const float* w_ie  = (const float*)d_in[4];  // [I,E]
    float* out = (float*)d_out;

    prep_pack<<<(EN * EWORDS) / 256, 256>>>(w_rec);
    prep_rest<<<8 + 256, 256>>>(w_ie, w_ei, x);
    sim_kernel<<<BN, NT>>>(x, w_ei, w_ie, out);
}